// round 4
// baseline (speedup 1.0000x reference)
#include <cuda_runtime.h>

#define NV 196608
#define DEG 9

typedef unsigned long long ull;

__device__ __forceinline__ ull pk2(float a, float b) {
    ull r; asm("mov.b64 %0, {%1,%2};" : "=l"(r) : "f"(a), "f"(b)); return r;
}
__device__ __forceinline__ void upk2(ull v, float& a, float& b) {
    asm("mov.b64 {%0,%1}, %2;" : "=f"(a), "=f"(b) : "l"(v));
}
__device__ __forceinline__ ull fma2(ull a, ull b, ull c) {
    ull d; asm("fma.rn.f32x2 %0, %1, %2, %3;" : "=l"(d) : "l"(a), "l"(b), "l"(c)); return d;
}

// ---------------- scratch ---------------------------------------------------
__device__ float g_xT[(size_t)NV * 32];   // [V, b0 f0-15 | b1 f0-15]
__device__ float g_t1[(size_t)NV * 32];   // L xT
__device__ float g_z1[(size_t)NV * 64];   // x0(W0-W2)+t1 W1   [V, b0 o0-31 | b1 o0-31]
__device__ float g_u1[(size_t)NV * 64];   // t1 * 2W2
__device__ float g_h1[(size_t)NV * 64];   // z1 + L u1
__device__ float g_t2[(size_t)NV * 64];   // L relu(bn1(h1))
__device__ float g_z2[(size_t)NV * 64];
__device__ float g_u2[(size_t)NV * 64];
__device__ float g_h2[(size_t)NV * 64];
__device__ float g_stats[128];            // [sum1, ss1, sum2, ss2] x32
__device__ float g_sb[128];               // [scale1, bias1, scale2, bias2] x32

// ---------------- K0 --------------------------------------------------------
__global__ void k_zero_stats() {
    if (threadIdx.x < 128) g_stats[threadIdx.x] = 0.0f;
}

// ---------------- K1: transpose x [B,V,16] -> xT [V,32] ---------------------
__global__ void k_transpose(const float* __restrict__ x) {
    const int total = NV * 8;
    for (int idx = blockIdx.x * blockDim.x + threadIdx.x; idx < total;
         idx += gridDim.x * blockDim.x) {
        int v = idx >> 3;
        int j = idx & 7;
        int c0 = j * 4;
        int b = c0 >> 4;
        int f = c0 & 15;
        float4 val = *(const float4*)(x + (size_t)b * NV * 16 + (size_t)v * 16 + f);
        *(float4*)(g_xT + (size_t)v * 32 + c0) = val;
    }
}

// ---------------- K2: t1 = L xT (pure gather, width 32) ---------------------
__global__ void k_gather32(const int* __restrict__ cols,
                           const float* __restrict__ vals) {
    int lane = threadIdx.x & 31;
    int gw = (blockIdx.x * blockDim.x + threadIdx.x) >> 5;
    int nw = (gridDim.x * blockDim.x) >> 5;
    for (int v = gw; v < NV; v += nw) {
        size_t eb = (size_t)v * DEG;
        int cj = 0; float aj = 0.0f;
        if (lane < DEG) { cj = cols[eb + lane]; aj = vals[eb + lane]; }
        int c9[DEG]; float a9[DEG], g9[DEG];
        #pragma unroll
        for (int j = 0; j < DEG; j++) {
            c9[j] = __shfl_sync(0xffffffffu, cj, j);
            a9[j] = __shfl_sync(0xffffffffu, aj, j);
        }
        #pragma unroll
        for (int j = 0; j < DEG; j++)
            g9[j] = g_xT[(size_t)c9[j] * 32 + lane];
        float s = 0.0f;
        #pragma unroll
        for (int j = 0; j < DEG; j++) s = fmaf(a9[j], g9[j], s);
        g_t1[(size_t)v * 32 + lane] = s;
    }
}

// ---------------- K3: dense layer1 GEMM ------------------------------------
// A[m=v][k] packed(b0,b1): k<16 -> xT, k>=16 -> t1.
// z1[.][n] = sum_k A*Wz (Wz: k<16 -> W0-W2, k>=16 -> W1)
// u1[.][n] = sum_{k>=16} A*Wu (Wu = 2 W2)
__global__ void __launch_bounds__(128) k_dense1(const float* __restrict__ W1) {
    __shared__ ull   sA[32][33];     // [v][k]
    __shared__ float sWz[32][32];
    __shared__ float sWu[16][32];
    int tid = threadIdx.x;
    for (int i = tid; i < 1024; i += 128) {
        int k = i >> 5, n = i & 31;
        sWz[k][n] = (k < 16) ? (W1[k * 32 + n] - W1[1024 + k * 32 + n])
                             : W1[512 + (k - 16) * 32 + n];
    }
    for (int i = tid; i < 512; i += 128) {
        int k = i >> 5, n = i & 31;
        sWu[k][n] = 2.0f * W1[1024 + k * 32 + n];
    }
    int v0 = blockIdx.x * 32;
    for (int i = tid; i < 1024; i += 128) {
        int v = i >> 5, k = i & 31;
        const float* src = (k < 16) ? (g_xT + (size_t)(v0 + v) * 32 + k)
                                    : (g_t1 + (size_t)(v0 + v) * 32 + (k - 16));
        sA[v][k] = pk2(src[0], src[16]);
    }
    __syncthreads();

    int tn = tid & 15, tm = tid >> 4;
    ull az[4][2], au[4][2];
    #pragma unroll
    for (int i = 0; i < 4; i++) { az[i][0] = 0; az[i][1] = 0; au[i][0] = 0; au[i][1] = 0; }

    #pragma unroll
    for (int k = 0; k < 16; k++) {
        float w0f = sWz[k][2 * tn], w1f = sWz[k][2 * tn + 1];
        ull w0 = pk2(w0f, w0f), w1 = pk2(w1f, w1f);
        #pragma unroll
        for (int im = 0; im < 4; im++) {
            ull a = sA[tm * 4 + im][k];
            az[im][0] = fma2(a, w0, az[im][0]);
            az[im][1] = fma2(a, w1, az[im][1]);
        }
    }
    #pragma unroll
    for (int k = 16; k < 32; k++) {
        float wz0f = sWz[k][2 * tn], wz1f = sWz[k][2 * tn + 1];
        float wu0f = sWu[k - 16][2 * tn], wu1f = sWu[k - 16][2 * tn + 1];
        ull wz0 = pk2(wz0f, wz0f), wz1 = pk2(wz1f, wz1f);
        ull wu0 = pk2(wu0f, wu0f), wu1 = pk2(wu1f, wu1f);
        #pragma unroll
        for (int im = 0; im < 4; im++) {
            ull a = sA[tm * 4 + im][k];
            az[im][0] = fma2(a, wz0, az[im][0]);
            az[im][1] = fma2(a, wz1, az[im][1]);
            au[im][0] = fma2(a, wu0, au[im][0]);
            au[im][1] = fma2(a, wu1, au[im][1]);
        }
    }
    #pragma unroll
    for (int im = 0; im < 4; im++) {
        int v = v0 + tm * 4 + im;
        float z00, z01, z10, z11, u00, u01, u10, u11;
        upk2(az[im][0], z00, z01); upk2(az[im][1], z10, z11);
        upk2(au[im][0], u00, u01); upk2(au[im][1], u10, u11);
        *(float2*)(g_z1 + (size_t)v * 64 + 2 * tn)      = make_float2(z00, z10);
        *(float2*)(g_z1 + (size_t)v * 64 + 32 + 2 * tn) = make_float2(z01, z11);
        *(float2*)(g_u1 + (size_t)v * 64 + 2 * tn)      = make_float2(u00, u10);
        *(float2*)(g_u1 + (size_t)v * 64 + 32 + 2 * tn) = make_float2(u01, u11);
    }
}

// ---------------- K4/K8: h = z + L u (width 64) + BN stats ------------------
__global__ void k_assemble(const int* __restrict__ cols,
                           const float* __restrict__ vals,
                           const float* __restrict__ zin,
                           const float* __restrict__ uin,
                           float* __restrict__ hout, int statsOff) {
    __shared__ float bsum[32], bss[32];
    int tid = threadIdx.x;
    if (tid < 32) { bsum[tid] = 0.0f; bss[tid] = 0.0f; }
    __syncthreads();
    int lane = tid & 31;
    int gw = (blockIdx.x * blockDim.x + tid) >> 5;
    int nw = (gridDim.x * blockDim.x) >> 5;
    float s0 = 0.0f, s1 = 0.0f, q0 = 0.0f, q1 = 0.0f;
    for (int v = gw; v < NV; v += nw) {
        size_t eb = (size_t)v * DEG;
        int cj = 0; float aj = 0.0f;
        if (lane < DEG) { cj = cols[eb + lane]; aj = vals[eb + lane]; }
        int c9[DEG]; float a9[DEG]; float2 g9[DEG];
        #pragma unroll
        for (int j = 0; j < DEG; j++) {
            c9[j] = __shfl_sync(0xffffffffu, cj, j);
            a9[j] = __shfl_sync(0xffffffffu, aj, j);
        }
        #pragma unroll
        for (int j = 0; j < DEG; j++)
            g9[j] = *(const float2*)(uin + (size_t)c9[j] * 64 + 2 * lane);
        float2 acc = *(const float2*)(zin + (size_t)v * 64 + 2 * lane);
        #pragma unroll
        for (int j = 0; j < DEG; j++) {
            acc.x = fmaf(a9[j], g9[j].x, acc.x);
            acc.y = fmaf(a9[j], g9[j].y, acc.y);
        }
        *(float2*)(hout + (size_t)v * 64 + 2 * lane) = acc;
        s0 += acc.x; q0 = fmaf(acc.x, acc.x, q0);
        s1 += acc.y; q1 = fmaf(acc.y, acc.y, q1);
    }
    int c0 = (2 * lane) & 31;
    atomicAdd(&bsum[c0], s0);     atomicAdd(&bss[c0], q0);
    atomicAdd(&bsum[c0 + 1], s1); atomicAdd(&bss[c0 + 1], q1);
    __syncthreads();
    if (tid < 32) {
        atomicAdd(&g_stats[statsOff + tid], bsum[tid]);
        atomicAdd(&g_stats[statsOff + 32 + tid], bss[tid]);
    }
}

// ---------------- K5: finalize BN stats -> scale/bias -----------------------
__global__ void k_finalize(const float* __restrict__ gamma,
                           const float* __restrict__ beta, int which) {
    int c = threadIdx.x;
    if (c >= 32) return;
    float n = (float)(2 * NV);
    float sum = g_stats[which * 64 + c];
    float ss = g_stats[which * 64 + 32 + c];
    float mean = sum / n;
    float var = ss / n - mean * mean;
    float rstd = rsqrtf(var + 1e-5f);
    float sc = gamma[c] * rstd;
    g_sb[which * 64 + c] = sc;
    g_sb[which * 64 + 32 + c] = beta[c] - mean * sc;
}

// ---------------- K6: t2 = L relu(bn1(h1)) (pure gather + bn) ---------------
__global__ void k_gather64_bn(const int* __restrict__ cols,
                              const float* __restrict__ vals) {
    int lane = threadIdx.x & 31;
    int gw = (blockIdx.x * blockDim.x + threadIdx.x) >> 5;
    int nw = (gridDim.x * blockDim.x) >> 5;
    int c0 = (2 * lane) & 31;
    float sc0 = g_sb[c0],     bi0 = g_sb[32 + c0];
    float sc1 = g_sb[c0 + 1], bi1 = g_sb[32 + c0 + 1];
    for (int v = gw; v < NV; v += nw) {
        size_t eb = (size_t)v * DEG;
        int cj = 0; float aj = 0.0f;
        if (lane < DEG) { cj = cols[eb + lane]; aj = vals[eb + lane]; }
        int c9[DEG]; float a9[DEG]; float2 g9[DEG];
        #pragma unroll
        for (int j = 0; j < DEG; j++) {
            c9[j] = __shfl_sync(0xffffffffu, cj, j);
            a9[j] = __shfl_sync(0xffffffffu, aj, j);
        }
        #pragma unroll
        for (int j = 0; j < DEG; j++)
            g9[j] = *(const float2*)(g_h1 + (size_t)c9[j] * 64 + 2 * lane);
        float sx = 0.0f, sy = 0.0f;
        #pragma unroll
        for (int j = 0; j < DEG; j++) {
            float r0 = fmaxf(fmaf(g9[j].x, sc0, bi0), 0.0f);
            float r1 = fmaxf(fmaf(g9[j].y, sc1, bi1), 0.0f);
            sx = fmaf(a9[j], r0, sx);
            sy = fmaf(a9[j], r1, sy);
        }
        float2 out; out.x = sx; out.y = sy;
        *(float2*)(g_t2 + (size_t)v * 64 + 2 * lane) = out;
    }
}

// ---------------- K7: dense layer2 GEMM ------------------------------------
// A[m=v][k] packed(b0,b1): k<32 -> relu(bn1(h1)), k>=32 -> t2.
__global__ void __launch_bounds__(128) k_dense2(const float* __restrict__ W2) {
    __shared__ ull   sA[32][65];
    __shared__ float sWz[64][32];
    __shared__ float sWu[32][32];
    __shared__ float sSc[32], sBi[32];
    int tid = threadIdx.x;
    if (tid < 32) { sSc[tid] = g_sb[tid]; sBi[tid] = g_sb[32 + tid]; }
    for (int i = tid; i < 2048; i += 128) {
        int k = i >> 5, n = i & 31;
        sWz[k][n] = (k < 32) ? (W2[k * 32 + n] - W2[2048 + k * 32 + n])
                             : W2[1024 + (k - 32) * 32 + n];
    }
    for (int i = tid; i < 1024; i += 128) {
        int k = i >> 5, n = i & 31;
        sWu[k][n] = 2.0f * W2[2048 + k * 32 + n];
    }
    __syncthreads();              // sSc/sBi ready before A staging uses them
    int v0 = blockIdx.x * 32;
    for (int i = tid; i < 2048; i += 128) {
        int v = i >> 6, k = i & 63;
        float a0, a1;
        if (k < 32) {
            float h0 = g_h1[(size_t)(v0 + v) * 64 + k];
            float h1v = g_h1[(size_t)(v0 + v) * 64 + 32 + k];
            a0 = fmaxf(fmaf(h0, sSc[k], sBi[k]), 0.0f);
            a1 = fmaxf(fmaf(h1v, sSc[k], sBi[k]), 0.0f);
        } else {
            int kk = k - 32;
            a0 = g_t2[(size_t)(v0 + v) * 64 + kk];
            a1 = g_t2[(size_t)(v0 + v) * 64 + 32 + kk];
        }
        sA[v][k] = pk2(a0, a1);
    }
    __syncthreads();

    int tn = tid & 15, tm = tid >> 4;
    ull az[4][2], au[4][2];
    #pragma unroll
    for (int i = 0; i < 4; i++) { az[i][0] = 0; az[i][1] = 0; au[i][0] = 0; au[i][1] = 0; }

    #pragma unroll
    for (int k = 0; k < 32; k++) {
        float w0f = sWz[k][2 * tn], w1f = sWz[k][2 * tn + 1];
        ull w0 = pk2(w0f, w0f), w1 = pk2(w1f, w1f);
        #pragma unroll
        for (int im = 0; im < 4; im++) {
            ull a = sA[tm * 4 + im][k];
            az[im][0] = fma2(a, w0, az[im][0]);
            az[im][1] = fma2(a, w1, az[im][1]);
        }
    }
    #pragma unroll
    for (int k = 32; k < 64; k++) {
        float wz0f = sWz[k][2 * tn], wz1f = sWz[k][2 * tn + 1];
        float wu0f = sWu[k - 32][2 * tn], wu1f = sWu[k - 32][2 * tn + 1];
        ull wz0 = pk2(wz0f, wz0f), wz1 = pk2(wz1f, wz1f);
        ull wu0 = pk2(wu0f, wu0f), wu1 = pk2(wu1f, wu1f);
        #pragma unroll
        for (int im = 0; im < 4; im++) {
            ull a = sA[tm * 4 + im][k];
            az[im][0] = fma2(a, wz0, az[im][0]);
            az[im][1] = fma2(a, wz1, az[im][1]);
            au[im][0] = fma2(a, wu0, au[im][0]);
            au[im][1] = fma2(a, wu1, au[im][1]);
        }
    }
    #pragma unroll
    for (int im = 0; im < 4; im++) {
        int v = v0 + tm * 4 + im;
        float z00, z01, z10, z11, u00, u01, u10, u11;
        upk2(az[im][0], z00, z01); upk2(az[im][1], z10, z11);
        upk2(au[im][0], u00, u01); upk2(au[im][1], u10, u11);
        *(float2*)(g_z2 + (size_t)v * 64 + 2 * tn)      = make_float2(z00, z10);
        *(float2*)(g_z2 + (size_t)v * 64 + 32 + 2 * tn) = make_float2(z01, z11);
        *(float2*)(g_u2 + (size_t)v * 64 + 2 * tn)      = make_float2(u00, u10);
        *(float2*)(g_u2 + (size_t)v * 64 + 32 + 2 * tn) = make_float2(u01, u11);
    }
}

// ---------------- K10: out = relu(bn2(h2)), layout [B,V,32] -----------------
__global__ void k_output(float* __restrict__ out) {
    const int total = NV * 16;
    for (int idx = blockIdx.x * blockDim.x + threadIdx.x; idx < total;
         idx += gridDim.x * blockDim.x) {
        int v = idx >> 4;
        int j = idx & 15;
        int col = j * 4;
        int ch = col & 31;
        int b = col >> 5;
        float4 hv = *(const float4*)(g_h2 + (size_t)v * 64 + col);
        float4 r;
        r.x = fmaxf(fmaf(hv.x, g_sb[64 + ch],     g_sb[96 + ch]),     0.0f);
        r.y = fmaxf(fmaf(hv.y, g_sb[64 + ch + 1], g_sb[96 + ch + 1]), 0.0f);
        r.z = fmaxf(fmaf(hv.z, g_sb[64 + ch + 2], g_sb[96 + ch + 2]), 0.0f);
        r.w = fmaxf(fmaf(hv.w, g_sb[64 + ch + 3], g_sb[96 + ch + 3]), 0.0f);
        *(float4*)(out + (size_t)b * NV * 32 + (size_t)v * 32 + ch) = r;
    }
}

// ---------------- launch ----------------------------------------------------
extern "C" void kernel_launch(void* const* d_in, const int* in_sizes, int n_in,
                              void* d_out, int out_size) {
    const float* x    = (const float*)d_in[0];
    const int*   cols = (const int*)d_in[2];
    const float* vals = (const float*)d_in[3];
    const float* W1   = (const float*)d_in[4];
    const float* g1   = (const float*)d_in[5];
    const float* b1   = (const float*)d_in[6];
    const float* W2   = (const float*)d_in[7];
    const float* g2   = (const float*)d_in[8];
    const float* b2   = (const float*)d_in[9];
    float*       out  = (float*)d_out;

    const int BLK = 256;
    const int GRID_G = 1184;          // 148 SMs * 8
    const int GRID_D = NV / 32;       // 6144

    float* zs1; cudaGetSymbolAddress((void**)&zs1, g_z1);
    float* us1; cudaGetSymbolAddress((void**)&us1, g_u1);
    float* hs1; cudaGetSymbolAddress((void**)&hs1, g_h1);
    float* zs2; cudaGetSymbolAddress((void**)&zs2, g_z2);
    float* us2; cudaGetSymbolAddress((void**)&us2, g_u2);
    float* hs2; cudaGetSymbolAddress((void**)&hs2, g_h2);

    k_zero_stats<<<1, 128>>>();
    k_transpose<<<2048, BLK>>>(x);
    k_gather32<<<GRID_G, BLK>>>(cols, vals);
    k_dense1<<<GRID_D, 128>>>(W1);
    k_assemble<<<GRID_G, BLK>>>(cols, vals, zs1, us1, hs1, 0);
    k_finalize<<<1, 32>>>(g1, b1, 0);
    k_gather64_bn<<<GRID_G, BLK>>>(cols, vals);
    k_dense2<<<GRID_D, 128>>>(W2);
    k_assemble<<<GRID_G, BLK>>>(cols, vals, zs2, us2, hs2, 64);
    k_finalize<<<1, 32>>>(g2, b2, 1);
    k_output<<<2048, BLK>>>(out);
}

// round 5
// speedup vs baseline: 1.0036x; 1.0036x over previous
#include <cuda_runtime.h>

#define NV 196608
#define DEG 9

// ---------------- scratch ---------------------------------------------------
__device__ float g_xT[(size_t)NV * 32];   // [V, b0 f0-15 | b1 f0-15]
__device__ float g_t1[(size_t)NV * 32];   // L xT
__device__ float g_h1[(size_t)NV * 64];   // layer1 pre-BN  [V, b0 o0-31 | b1 o0-31]
__device__ float g_t2[(size_t)NV * 64];   // L relu(bn1(h1))
__device__ float g_h2[(size_t)NV * 64];   // layer2 pre-BN
__device__ float g_stats[128];            // [sum1, ss1, sum2, ss2] x32
__device__ float g_sb[128];               // [scale1, bias1, scale2, bias2] x32

// ---------------- K0 --------------------------------------------------------
__global__ void k_zero_stats() {
    if (threadIdx.x < 128) g_stats[threadIdx.x] = 0.0f;
}

// ---------------- K1: transpose x [B,V,16] -> xT [V,32] ---------------------
__global__ void k_transpose(const float* __restrict__ x) {
    const int total = NV * 8;
    for (int idx = blockIdx.x * blockDim.x + threadIdx.x; idx < total;
         idx += gridDim.x * blockDim.x) {
        int v = idx >> 3;
        int j = idx & 7;
        int c0 = j * 4;
        int b = c0 >> 4;
        int f = c0 & 15;
        float4 val = *(const float4*)(x + (size_t)b * NV * 16 + (size_t)v * 16 + f);
        *(float4*)(g_xT + (size_t)v * 32 + c0) = val;
    }
}

// ---------------- K2: t1 = L xT (pure gather, width 32) ---------------------
__global__ void k_spmv32(const int* __restrict__ cols,
                         const float* __restrict__ vals) {
    int lane = threadIdx.x & 31;
    int gw = (blockIdx.x * blockDim.x + threadIdx.x) >> 5;
    int nw = (gridDim.x * blockDim.x) >> 5;
    for (int v = gw; v < NV; v += nw) {
        size_t eb = (size_t)v * DEG;
        int cj = 0; float aj = 0.0f;
        if (lane < DEG) { cj = cols[eb + lane]; aj = vals[eb + lane]; }
        float g9[DEG];
        #pragma unroll
        for (int j = 0; j < DEG; j++) {
            int c = __shfl_sync(0xffffffffu, cj, j);
            g9[j] = g_xT[(size_t)c * 32 + lane];
        }
        float s = 0.0f;
        #pragma unroll
        for (int j = 0; j < DEG; j++) {
            float a = __shfl_sync(0xffffffffu, aj, j);
            s = fmaf(a, g9[j], s);
        }
        g_t1[(size_t)v * 32 + lane] = s;
    }
}

// ---------------- K3: fused layer1 ------------------------------------------
// s = L t1 (gather); h1 = x0*(W0-W2) + t1*W1 + s*(2W2); BN stats.
// Weights in registers (lane = output channel o). Inputs staged per warp as
// float4 (b0 f, b1 f, b0 f+1, b1 f+1) -> one LDS.128 broadcast per (arr, fpair).
__global__ void __launch_bounds__(128) k_fused1(const int* __restrict__ cols,
                                                const float* __restrict__ vals,
                                                const float* __restrict__ W1) {
    __shared__ float4 sIn[4][3][8];          // [warp][arr][fpair]
    __shared__ float bsum[32], bss[32];
    int tid = threadIdx.x, lane = tid & 31, w = tid >> 5;
    if (tid < 32) { bsum[tid] = 0.0f; bss[tid] = 0.0f; }
    float wz[16], ww[16], wu[16];
    #pragma unroll
    for (int f = 0; f < 16; f++) {
        float a = W1[f * 32 + lane];
        float b = W1[512 + f * 32 + lane];
        float c = W1[1024 + f * 32 + lane];
        wz[f] = a - c; ww[f] = b; wu[f] = 2.0f * c;
    }
    __syncthreads();

    int bb = lane >> 4, ff = lane & 15;      // this lane's input-col mapping
    int wi = ff * 2 + bb;                    // staging word within an arr
    float* sInW = (float*)sIn[w];            // arr stride = 32 floats
    int gw = blockIdx.x * 4 + w, nw = gridDim.x * 4;
    float ls = 0.0f, lss = 0.0f;

    for (int v = gw; v < NV; v += nw) {
        size_t eb = (size_t)v * DEG;
        int cj = 0; float aj = 0.0f;
        if (lane < DEG) { cj = cols[eb + lane]; aj = vals[eb + lane]; }
        float g9[DEG];
        #pragma unroll
        for (int j = 0; j < DEG; j++) {
            int c = __shfl_sync(0xffffffffu, cj, j);
            g9[j] = g_t1[(size_t)c * 32 + lane];
        }
        float s = 0.0f;
        #pragma unroll
        for (int j = 0; j < DEG; j++) {
            float a = __shfl_sync(0xffffffffu, aj, j);
            s = fmaf(a, g9[j], s);
        }
        float xv = g_xT[(size_t)v * 32 + lane];
        float tv = g_t1[(size_t)v * 32 + lane];
        sInW[wi] = xv; sInW[32 + wi] = tv; sInW[64 + wi] = s;
        __syncwarp();
        float acc0 = 0.0f, acc1 = 0.0f;
        #pragma unroll
        for (int fp = 0; fp < 8; fp++) {
            float4 px = sIn[w][0][fp];
            acc0 = fmaf(px.x, wz[2 * fp], acc0);     acc1 = fmaf(px.y, wz[2 * fp], acc1);
            acc0 = fmaf(px.z, wz[2 * fp + 1], acc0); acc1 = fmaf(px.w, wz[2 * fp + 1], acc1);
            float4 pt = sIn[w][1][fp];
            acc0 = fmaf(pt.x, ww[2 * fp], acc0);     acc1 = fmaf(pt.y, ww[2 * fp], acc1);
            acc0 = fmaf(pt.z, ww[2 * fp + 1], acc0); acc1 = fmaf(pt.w, ww[2 * fp + 1], acc1);
            float4 ps = sIn[w][2][fp];
            acc0 = fmaf(ps.x, wu[2 * fp], acc0);     acc1 = fmaf(ps.y, wu[2 * fp], acc1);
            acc0 = fmaf(ps.z, wu[2 * fp + 1], acc0); acc1 = fmaf(ps.w, wu[2 * fp + 1], acc1);
        }
        __syncwarp();
        g_h1[(size_t)v * 64 + lane] = acc0;
        g_h1[(size_t)v * 64 + 32 + lane] = acc1;
        ls += acc0 + acc1;
        lss = fmaf(acc0, acc0, lss);
        lss = fmaf(acc1, acc1, lss);
    }
    atomicAdd(&bsum[lane], ls);
    atomicAdd(&bss[lane], lss);
    __syncthreads();
    if (tid < 32) {
        atomicAdd(&g_stats[tid], bsum[tid]);
        atomicAdd(&g_stats[32 + tid], bss[tid]);
    }
}

// ---------------- K4: finalize BN stats -> scale/bias -----------------------
__global__ void k_finalize(const float* __restrict__ gamma,
                           const float* __restrict__ beta, int which) {
    int c = threadIdx.x;
    if (c >= 32) return;
    float n = (float)(2 * NV);
    float sum = g_stats[which * 64 + c];
    float ss = g_stats[which * 64 + 32 + c];
    float mean = sum / n;
    float var = ss / n - mean * mean;
    float rstd = rsqrtf(var + 1e-5f);
    float sc = gamma[c] * rstd;
    g_sb[which * 64 + c] = sc;
    g_sb[which * 64 + 32 + c] = beta[c] - mean * sc;
}

// ---------------- K5: t2 = L relu(bn1(h1)) (pure gather + bn) ---------------
__global__ void k_spmv64_bn(const int* __restrict__ cols,
                            const float* __restrict__ vals) {
    int lane = threadIdx.x & 31;
    int gw = (blockIdx.x * blockDim.x + threadIdx.x) >> 5;
    int nw = (gridDim.x * blockDim.x) >> 5;
    int c0 = (2 * lane) & 31;
    float sc0 = g_sb[c0],     bi0 = g_sb[32 + c0];
    float sc1 = g_sb[c0 + 1], bi1 = g_sb[32 + c0 + 1];
    for (int v = gw; v < NV; v += nw) {
        size_t eb = (size_t)v * DEG;
        int cj = 0; float aj = 0.0f;
        if (lane < DEG) { cj = cols[eb + lane]; aj = vals[eb + lane]; }
        float2 g9[DEG];
        #pragma unroll
        for (int j = 0; j < DEG; j++) {
            int c = __shfl_sync(0xffffffffu, cj, j);
            g9[j] = *(const float2*)(g_h1 + (size_t)c * 64 + 2 * lane);
        }
        float sx = 0.0f, sy = 0.0f;
        #pragma unroll
        for (int j = 0; j < DEG; j++) {
            float a = __shfl_sync(0xffffffffu, aj, j);
            float r0 = fmaxf(fmaf(g9[j].x, sc0, bi0), 0.0f);
            float r1 = fmaxf(fmaf(g9[j].y, sc1, bi1), 0.0f);
            sx = fmaf(a, r0, sx);
            sy = fmaf(a, r1, sy);
        }
        float2 out; out.x = sx; out.y = sy;
        *(float2*)(g_t2 + (size_t)v * 64 + 2 * lane) = out;
    }
}

// ---------------- K6: fused layer2 ------------------------------------------
// s = L t2 (gather); h2 = a1*(W0-W2) + t2*W1 + s*(2W2), a1 = relu(bn1(h1)).
// Weights: 96 registers/lane (lane = output o, shared by both batch accs).
__global__ void __launch_bounds__(128) k_fused2(const int* __restrict__ cols,
                                                const float* __restrict__ vals,
                                                const float* __restrict__ W2) {
    __shared__ float4 sIn[4][3][16];         // [warp][arr][fpair]
    __shared__ float bsum[32], bss[32];
    int tid = threadIdx.x, lane = tid & 31, w = tid >> 5;
    if (tid < 32) { bsum[tid] = 0.0f; bss[tid] = 0.0f; }
    float wa[32], wt[32], ws[32];
    #pragma unroll
    for (int f = 0; f < 32; f++) {
        float a = W2[f * 32 + lane];
        float b = W2[1024 + f * 32 + lane];
        float c = W2[2048 + f * 32 + lane];
        wa[f] = a - c; wt[f] = b; ws[f] = 2.0f * c;
    }
    int m = lane & 15, bb = lane >> 4;
    int ch0 = 2 * m, ch1 = 2 * m + 1;        // channels of this lane's held cols
    float sc0 = g_sb[ch0], bi0 = g_sb[32 + ch0];
    float sc1 = g_sb[ch1], bi1 = g_sb[32 + ch1];
    __syncthreads();

    int colOff = bb * 32 + 2 * m;            // base col this lane reads (f=2m,2m+1)
    int wi0 = 4 * m + bb, wi1 = 4 * m + 2 + bb;  // staging words within an arr
    float* sInW = (float*)sIn[w];            // arr stride = 64 floats
    int gw = blockIdx.x * 4 + w, nw = gridDim.x * 4;
    float ls = 0.0f, lss = 0.0f;

    for (int v = gw; v < NV; v += nw) {
        size_t eb = (size_t)v * DEG;
        int cj = 0; float aj = 0.0f;
        if (lane < DEG) { cj = cols[eb + lane]; aj = vals[eb + lane]; }
        float2 g9[DEG];
        #pragma unroll
        for (int j = 0; j < DEG; j++) {
            int c = __shfl_sync(0xffffffffu, cj, j);
            g9[j] = *(const float2*)(g_t2 + (size_t)c * 64 + colOff);
        }
        float sx = 0.0f, sy = 0.0f;
        #pragma unroll
        for (int j = 0; j < DEG; j++) {
            float a = __shfl_sync(0xffffffffu, aj, j);
            sx = fmaf(a, g9[j].x, sx);
            sy = fmaf(a, g9[j].y, sy);
        }
        float2 hv = *(const float2*)(g_h1 + (size_t)v * 64 + colOff);
        float a1x = fmaxf(fmaf(hv.x, sc0, bi0), 0.0f);
        float a1y = fmaxf(fmaf(hv.y, sc1, bi1), 0.0f);
        float2 tv = *(const float2*)(g_t2 + (size_t)v * 64 + colOff);

        sInW[wi0] = a1x;        sInW[wi1] = a1y;
        sInW[64 + wi0] = tv.x;  sInW[64 + wi1] = tv.y;
        sInW[128 + wi0] = sx;   sInW[128 + wi1] = sy;
        __syncwarp();
        float acc0 = 0.0f, acc1 = 0.0f;
        #pragma unroll
        for (int fp = 0; fp < 16; fp++) {
            float4 pa = sIn[w][0][fp];
            acc0 = fmaf(pa.x, wa[2 * fp], acc0);     acc1 = fmaf(pa.y, wa[2 * fp], acc1);
            acc0 = fmaf(pa.z, wa[2 * fp + 1], acc0); acc1 = fmaf(pa.w, wa[2 * fp + 1], acc1);
            float4 pt = sIn[w][1][fp];
            acc0 = fmaf(pt.x, wt[2 * fp], acc0);     acc1 = fmaf(pt.y, wt[2 * fp], acc1);
            acc0 = fmaf(pt.z, wt[2 * fp + 1], acc0); acc1 = fmaf(pt.w, wt[2 * fp + 1], acc1);
            float4 ps = sIn[w][2][fp];
            acc0 = fmaf(ps.x, ws[2 * fp], acc0);     acc1 = fmaf(ps.y, ws[2 * fp], acc1);
            acc0 = fmaf(ps.z, ws[2 * fp + 1], acc0); acc1 = fmaf(ps.w, ws[2 * fp + 1], acc1);
        }
        __syncwarp();
        g_h2[(size_t)v * 64 + lane] = acc0;
        g_h2[(size_t)v * 64 + 32 + lane] = acc1;
        ls += acc0 + acc1;
        lss = fmaf(acc0, acc0, lss);
        lss = fmaf(acc1, acc1, lss);
    }
    atomicAdd(&bsum[lane], ls);
    atomicAdd(&bss[lane], lss);
    __syncthreads();
    if (tid < 32) {
        atomicAdd(&g_stats[64 + tid], bsum[tid]);
        atomicAdd(&g_stats[96 + tid], bss[tid]);
    }
}

// ---------------- K7: out = relu(bn2(h2)), layout [B,V,32] ------------------
__global__ void k_output(float* __restrict__ out) {
    const int total = NV * 16;
    for (int idx = blockIdx.x * blockDim.x + threadIdx.x; idx < total;
         idx += gridDim.x * blockDim.x) {
        int v = idx >> 4;
        int j = idx & 15;
        int col = j * 4;
        int ch = col & 31;
        int b = col >> 5;
        float4 hv = *(const float4*)(g_h2 + (size_t)v * 64 + col);
        float4 r;
        r.x = fmaxf(fmaf(hv.x, g_sb[64 + ch],     g_sb[96 + ch]),     0.0f);
        r.y = fmaxf(fmaf(hv.y, g_sb[64 + ch + 1], g_sb[96 + ch + 1]), 0.0f);
        r.z = fmaxf(fmaf(hv.z, g_sb[64 + ch + 2], g_sb[96 + ch + 2]), 0.0f);
        r.w = fmaxf(fmaf(hv.w, g_sb[64 + ch + 3], g_sb[96 + ch + 3]), 0.0f);
        *(float4*)(out + (size_t)b * NV * 32 + (size_t)v * 32 + ch) = r;
    }
}

// ---------------- launch ----------------------------------------------------
extern "C" void kernel_launch(void* const* d_in, const int* in_sizes, int n_in,
                              void* d_out, int out_size) {
    const float* x    = (const float*)d_in[0];
    const int*   cols = (const int*)d_in[2];
    const float* vals = (const float*)d_in[3];
    const float* W1   = (const float*)d_in[4];
    const float* g1   = (const float*)d_in[5];
    const float* b1   = (const float*)d_in[6];
    const float* W2   = (const float*)d_in[7];
    const float* g2   = (const float*)d_in[8];
    const float* b2   = (const float*)d_in[9];
    float*       out  = (float*)d_out;

    const int GRID_G = 1184;      // 256-thread gather kernels: 9472 warps
    const int GRID_F = 2368;      // 128-thread fused kernels:  9472 warps

    k_zero_stats<<<1, 128>>>();
    k_transpose<<<2048, 256>>>(x);
    k_spmv32<<<GRID_G, 256>>>(cols, vals);
    k_fused1<<<GRID_F, 128>>>(cols, vals, W1);
    k_finalize<<<1, 32>>>(g1, b1, 0);
    k_spmv64_bn<<<GRID_G, 256>>>(cols, vals);
    k_fused2<<<GRID_F, 128>>>(cols, vals, W2);
    k_finalize<<<1, 32>>>(g2, b2, 1);
    k_output<<<2048, 256>>>(out);
}

// round 6
// speedup vs baseline: 1.4357x; 1.4305x over previous
#include <cuda_runtime.h>

#define NV 196608
#define DEG 9

// ---------------- scratch ---------------------------------------------------
__device__ float g_xT[(size_t)NV * 32];   // [V, b0 f0-15 | b1 f0-15]
__device__ float g_t1[(size_t)NV * 32];   // L xT
__device__ float g_h1[(size_t)NV * 64];   // layer1 pre-BN  [V, b0 o0-31 | b1 o0-31]
__device__ float g_t2[(size_t)NV * 64];   // L relu(bn1(h1))
__device__ float g_h2[(size_t)NV * 64];   // layer2 pre-BN
__device__ float g_stats[128];            // [sum1, ss1, sum2, ss2] x32
__device__ float g_sb[128];               // [scale1, bias1, scale2, bias2] x32

// ---------------- K0 --------------------------------------------------------
__global__ void k_zero_stats() {
    if (threadIdx.x < 128) g_stats[threadIdx.x] = 0.0f;
}

// ---------------- K1: transpose x [B,V,16] -> xT [V,32] ---------------------
__global__ void k_transpose(const float* __restrict__ x) {
    const int total = NV * 8;
    for (int idx = blockIdx.x * blockDim.x + threadIdx.x; idx < total;
         idx += gridDim.x * blockDim.x) {
        int v = idx >> 3;
        int j = idx & 7;
        int c0 = j * 4;
        int b = c0 >> 4;
        int f = c0 & 15;
        float4 val = *(const float4*)(x + (size_t)b * NV * 16 + (size_t)v * 16 + f);
        *(float4*)(g_xT + (size_t)v * 32 + c0) = val;
    }
}

// ---------------- K2: t1 = L xT (4 vertices/warp, float4 lanes) -------------
__global__ void k_spmv32(const int* __restrict__ cols,
                         const float* __restrict__ vals) {
    int lane = threadIdx.x & 31;
    int q = lane >> 3, r = lane & 7;         // slot, quad-col
    int gw = (blockIdx.x * blockDim.x + threadIdx.x) >> 5;
    int nw = (gridDim.x * blockDim.x) >> 5;
    for (int v0 = gw * 4; v0 < NV; v0 += nw * 4) {
        int v = v0 + q;
        int eb = v * DEG;
        int   cj = cols[eb + r];             // edges 0..7 of this slot
        float aj = vals[eb + r];
        int   c8 = cols[eb + 8];             // edge 8, uniform per slot
        float a8 = vals[eb + 8];
        float4 acc = make_float4(0.f, 0.f, 0.f, 0.f);
        #pragma unroll
        for (int j = 0; j < 8; j++) {
            int   c = __shfl_sync(0xffffffffu, cj, (q << 3) + j);
            float a = __shfl_sync(0xffffffffu, aj, (q << 3) + j);
            float4 g = *(const float4*)(g_xT + (size_t)c * 32 + 4 * r);
            acc.x = fmaf(a, g.x, acc.x); acc.y = fmaf(a, g.y, acc.y);
            acc.z = fmaf(a, g.z, acc.z); acc.w = fmaf(a, g.w, acc.w);
        }
        {
            float4 g = *(const float4*)(g_xT + (size_t)c8 * 32 + 4 * r);
            acc.x = fmaf(a8, g.x, acc.x); acc.y = fmaf(a8, g.y, acc.y);
            acc.z = fmaf(a8, g.z, acc.z); acc.w = fmaf(a8, g.w, acc.w);
        }
        *(float4*)(g_t1 + (size_t)v * 32 + 4 * r) = acc;
    }
}

// ---------------- K3: fused layer1 (4 vertices/warp) ------------------------
// s = L t1; h1 = x*(W0-W2) + t1*W1 + s*(2W2); BN stats.
__global__ void __launch_bounds__(128) k_fused1(const int* __restrict__ cols,
                                                const float* __restrict__ vals,
                                                const float* __restrict__ W1) {
    __shared__ float4 sIn[4][4][3][8];       // [warp][slot][arr][quad]
    __shared__ float bsum[32], bss[32];
    int tid = threadIdx.x, lane = tid & 31, w = tid >> 5;
    int q = lane >> 3, r = lane & 7;
    if (tid < 32) { bsum[tid] = 0.0f; bss[tid] = 0.0f; }
    float wz[16], ww[16], wu[16];
    #pragma unroll
    for (int f = 0; f < 16; f++) {
        float a = W1[f * 32 + lane];
        float b = W1[512 + f * 32 + lane];
        float c = W1[1024 + f * 32 + lane];
        wz[f] = a - c; ww[f] = b; wu[f] = 2.0f * c;
    }
    __syncthreads();

    int gw = blockIdx.x * 4 + w, nw = gridDim.x * 4;
    float ls = 0.0f, lss = 0.0f;

    for (int v0 = gw * 4; v0 < NV; v0 += nw * 4) {
        int v = v0 + q;
        int eb = v * DEG;
        int   cj = cols[eb + r];
        float aj = vals[eb + r];
        int   c8 = cols[eb + 8];
        float a8 = vals[eb + 8];
        float4 s4 = make_float4(0.f, 0.f, 0.f, 0.f);
        #pragma unroll
        for (int j = 0; j < 8; j++) {
            int   c = __shfl_sync(0xffffffffu, cj, (q << 3) + j);
            float a = __shfl_sync(0xffffffffu, aj, (q << 3) + j);
            float4 g = *(const float4*)(g_t1 + (size_t)c * 32 + 4 * r);
            s4.x = fmaf(a, g.x, s4.x); s4.y = fmaf(a, g.y, s4.y);
            s4.z = fmaf(a, g.z, s4.z); s4.w = fmaf(a, g.w, s4.w);
        }
        {
            float4 g = *(const float4*)(g_t1 + (size_t)c8 * 32 + 4 * r);
            s4.x = fmaf(a8, g.x, s4.x); s4.y = fmaf(a8, g.y, s4.y);
            s4.z = fmaf(a8, g.z, s4.z); s4.w = fmaf(a8, g.w, s4.w);
        }
        float4 x4 = *(const float4*)(g_xT + (size_t)v * 32 + 4 * r);
        float4 t4 = *(const float4*)(g_t1 + (size_t)v * 32 + 4 * r);
        sIn[w][q][0][r] = x4;
        sIn[w][q][1][r] = t4;
        sIn[w][q][2][r] = s4;
        __syncwarp();
        #pragma unroll
        for (int q2 = 0; q2 < 4; q2++) {
            float acc0 = 0.0f, acc1 = 0.0f;
            #pragma unroll
            for (int fp = 0; fp < 4; fp++) {     // f quad, b0 at fp, b1 at fp+4
                float4 pa = sIn[w][q2][0][fp];
                float4 pb = sIn[w][q2][0][fp + 4];
                acc0 = fmaf(pa.x, wz[4*fp], acc0);   acc1 = fmaf(pb.x, wz[4*fp], acc1);
                acc0 = fmaf(pa.y, wz[4*fp+1], acc0); acc1 = fmaf(pb.y, wz[4*fp+1], acc1);
                acc0 = fmaf(pa.z, wz[4*fp+2], acc0); acc1 = fmaf(pb.z, wz[4*fp+2], acc1);
                acc0 = fmaf(pa.w, wz[4*fp+3], acc0); acc1 = fmaf(pb.w, wz[4*fp+3], acc1);
                float4 ta = sIn[w][q2][1][fp];
                float4 tb = sIn[w][q2][1][fp + 4];
                acc0 = fmaf(ta.x, ww[4*fp], acc0);   acc1 = fmaf(tb.x, ww[4*fp], acc1);
                acc0 = fmaf(ta.y, ww[4*fp+1], acc0); acc1 = fmaf(tb.y, ww[4*fp+1], acc1);
                acc0 = fmaf(ta.z, ww[4*fp+2], acc0); acc1 = fmaf(tb.z, ww[4*fp+2], acc1);
                acc0 = fmaf(ta.w, ww[4*fp+3], acc0); acc1 = fmaf(tb.w, ww[4*fp+3], acc1);
                float4 sa = sIn[w][q2][2][fp];
                float4 sb = sIn[w][q2][2][fp + 4];
                acc0 = fmaf(sa.x, wu[4*fp], acc0);   acc1 = fmaf(sb.x, wu[4*fp], acc1);
                acc0 = fmaf(sa.y, wu[4*fp+1], acc0); acc1 = fmaf(sb.y, wu[4*fp+1], acc1);
                acc0 = fmaf(sa.z, wu[4*fp+2], acc0); acc1 = fmaf(sb.z, wu[4*fp+2], acc1);
                acc0 = fmaf(sa.w, wu[4*fp+3], acc0); acc1 = fmaf(sb.w, wu[4*fp+3], acc1);
            }
            g_h1[(size_t)(v0 + q2) * 64 + lane] = acc0;
            g_h1[(size_t)(v0 + q2) * 64 + 32 + lane] = acc1;
            ls += acc0 + acc1;
            lss = fmaf(acc0, acc0, lss);
            lss = fmaf(acc1, acc1, lss);
        }
        __syncwarp();
    }
    atomicAdd(&bsum[lane], ls);
    atomicAdd(&bss[lane], lss);
    __syncthreads();
    if (tid < 32) {
        atomicAdd(&g_stats[tid], bsum[tid]);
        atomicAdd(&g_stats[32 + tid], bss[tid]);
    }
}

// ---------------- K4: finalize BN stats -> scale/bias -----------------------
__global__ void k_finalize(const float* __restrict__ gamma,
                           const float* __restrict__ beta, int which) {
    int c = threadIdx.x;
    if (c >= 32) return;
    float n = (float)(2 * NV);
    float sum = g_stats[which * 64 + c];
    float ss = g_stats[which * 64 + 32 + c];
    float mean = sum / n;
    float var = ss / n - mean * mean;
    float rstd = rsqrtf(var + 1e-5f);
    float sc = gamma[c] * rstd;
    g_sb[which * 64 + c] = sc;
    g_sb[which * 64 + 32 + c] = beta[c] - mean * sc;
}

// ---------------- K5: t2 = L relu(bn1(h1)) (2 vertices/warp) ----------------
__global__ void k_spmv64_bn(const int* __restrict__ cols,
                            const float* __restrict__ vals) {
    int lane = threadIdx.x & 31;
    int q = lane >> 4, r = lane & 15;
    int gw = (blockIdx.x * blockDim.x + threadIdx.x) >> 5;
    int nw = (gridDim.x * blockDim.x) >> 5;
    int ch = (4 * r) & 31;
    float4 sc4 = *(const float4*)(g_sb + ch);
    float4 bi4 = *(const float4*)(g_sb + 32 + ch);
    for (int v0 = gw * 2; v0 < NV; v0 += nw * 2) {
        int v = v0 + q;
        int eb = v * DEG;
        int   cj = (r < 8) ? cols[eb + r] : 0;
        float aj = (r < 8) ? vals[eb + r] : 0.0f;
        int   c8 = cols[eb + 8];
        float a8 = vals[eb + 8];
        float4 acc = make_float4(0.f, 0.f, 0.f, 0.f);
        #pragma unroll
        for (int j = 0; j < 8; j++) {
            int   c = __shfl_sync(0xffffffffu, cj, (q << 4) + j);
            float a = __shfl_sync(0xffffffffu, aj, (q << 4) + j);
            float4 g = *(const float4*)(g_h1 + (size_t)c * 64 + 4 * r);
            acc.x = fmaf(a, fmaxf(fmaf(g.x, sc4.x, bi4.x), 0.0f), acc.x);
            acc.y = fmaf(a, fmaxf(fmaf(g.y, sc4.y, bi4.y), 0.0f), acc.y);
            acc.z = fmaf(a, fmaxf(fmaf(g.z, sc4.z, bi4.z), 0.0f), acc.z);
            acc.w = fmaf(a, fmaxf(fmaf(g.w, sc4.w, bi4.w), 0.0f), acc.w);
        }
        {
            float4 g = *(const float4*)(g_h1 + (size_t)c8 * 64 + 4 * r);
            acc.x = fmaf(a8, fmaxf(fmaf(g.x, sc4.x, bi4.x), 0.0f), acc.x);
            acc.y = fmaf(a8, fmaxf(fmaf(g.y, sc4.y, bi4.y), 0.0f), acc.y);
            acc.z = fmaf(a8, fmaxf(fmaf(g.z, sc4.z, bi4.z), 0.0f), acc.z);
            acc.w = fmaf(a8, fmaxf(fmaf(g.w, sc4.w, bi4.w), 0.0f), acc.w);
        }
        *(float4*)(g_t2 + (size_t)v * 64 + 4 * r) = acc;
    }
}

// ---------------- K6: fused layer2 (2 vertices/warp) ------------------------
// s = L t2; h2 = a1*(W0-W2) + t2*W1 + s*(2W2), a1 = relu(bn1(h1)); BN stats.
__global__ void __launch_bounds__(128) k_fused2(const int* __restrict__ cols,
                                                const float* __restrict__ vals,
                                                const float* __restrict__ W2) {
    __shared__ float4 sIn[4][2][3][16];      // [warp][slot][arr][quad]
    __shared__ float bsum[32], bss[32];
    int tid = threadIdx.x, lane = tid & 31, w = tid >> 5;
    int q = lane >> 4, r = lane & 15;
    if (tid < 32) { bsum[tid] = 0.0f; bss[tid] = 0.0f; }
    float wa[32], wt[32], ws[32];
    #pragma unroll
    for (int f = 0; f < 32; f++) {
        float a = W2[f * 32 + lane];
        float b = W2[1024 + f * 32 + lane];
        float c = W2[2048 + f * 32 + lane];
        wa[f] = a - c; wt[f] = b; ws[f] = 2.0f * c;
    }
    int ch = (4 * r) & 31;
    float4 sc4 = *(const float4*)(g_sb + ch);
    float4 bi4 = *(const float4*)(g_sb + 32 + ch);
    __syncthreads();

    int gw = blockIdx.x * 4 + w, nw = gridDim.x * 4;
    float ls = 0.0f, lss = 0.0f;

    for (int v0 = gw * 2; v0 < NV; v0 += nw * 2) {
        int v = v0 + q;
        int eb = v * DEG;
        int   cj = (r < 8) ? cols[eb + r] : 0;
        float aj = (r < 8) ? vals[eb + r] : 0.0f;
        int   c8 = cols[eb + 8];
        float a8 = vals[eb + 8];
        float4 s4 = make_float4(0.f, 0.f, 0.f, 0.f);
        #pragma unroll
        for (int j = 0; j < 8; j++) {
            int   c = __shfl_sync(0xffffffffu, cj, (q << 4) + j);
            float a = __shfl_sync(0xffffffffu, aj, (q << 4) + j);
            float4 g = *(const float4*)(g_t2 + (size_t)c * 64 + 4 * r);
            s4.x = fmaf(a, g.x, s4.x); s4.y = fmaf(a, g.y, s4.y);
            s4.z = fmaf(a, g.z, s4.z); s4.w = fmaf(a, g.w, s4.w);
        }
        {
            float4 g = *(const float4*)(g_t2 + (size_t)c8 * 64 + 4 * r);
            s4.x = fmaf(a8, g.x, s4.x); s4.y = fmaf(a8, g.y, s4.y);
            s4.z = fmaf(a8, g.z, s4.z); s4.w = fmaf(a8, g.w, s4.w);
        }
        float4 hv = *(const float4*)(g_h1 + (size_t)v * 64 + 4 * r);
        float4 a14;
        a14.x = fmaxf(fmaf(hv.x, sc4.x, bi4.x), 0.0f);
        a14.y = fmaxf(fmaf(hv.y, sc4.y, bi4.y), 0.0f);
        a14.z = fmaxf(fmaf(hv.z, sc4.z, bi4.z), 0.0f);
        a14.w = fmaxf(fmaf(hv.w, sc4.w, bi4.w), 0.0f);
        float4 t4 = *(const float4*)(g_t2 + (size_t)v * 64 + 4 * r);
        sIn[w][q][0][r] = a14;
        sIn[w][q][1][r] = t4;
        sIn[w][q][2][r] = s4;
        __syncwarp();
        #pragma unroll
        for (int q2 = 0; q2 < 2; q2++) {
            float acc0 = 0.0f, acc1 = 0.0f;
            #pragma unroll
            for (int fp = 0; fp < 8; fp++) {     // f quad, b0 at fp, b1 at fp+8
                float4 pa = sIn[w][q2][0][fp];
                float4 pb = sIn[w][q2][0][fp + 8];
                acc0 = fmaf(pa.x, wa[4*fp], acc0);   acc1 = fmaf(pb.x, wa[4*fp], acc1);
                acc0 = fmaf(pa.y, wa[4*fp+1], acc0); acc1 = fmaf(pb.y, wa[4*fp+1], acc1);
                acc0 = fmaf(pa.z, wa[4*fp+2], acc0); acc1 = fmaf(pb.z, wa[4*fp+2], acc1);
                acc0 = fmaf(pa.w, wa[4*fp+3], acc0); acc1 = fmaf(pb.w, wa[4*fp+3], acc1);
                float4 ta = sIn[w][q2][1][fp];
                float4 tb = sIn[w][q2][1][fp + 8];
                acc0 = fmaf(ta.x, wt[4*fp], acc0);   acc1 = fmaf(tb.x, wt[4*fp], acc1);
                acc0 = fmaf(ta.y, wt[4*fp+1], acc0); acc1 = fmaf(tb.y, wt[4*fp+1], acc1);
                acc0 = fmaf(ta.z, wt[4*fp+2], acc0); acc1 = fmaf(tb.z, wt[4*fp+2], acc1);
                acc0 = fmaf(ta.w, wt[4*fp+3], acc0); acc1 = fmaf(tb.w, wt[4*fp+3], acc1);
                float4 sa = sIn[w][q2][2][fp];
                float4 sb = sIn[w][q2][2][fp + 8];
                acc0 = fmaf(sa.x, ws[4*fp], acc0);   acc1 = fmaf(sb.x, ws[4*fp], acc1);
                acc0 = fmaf(sa.y, ws[4*fp+1], acc0); acc1 = fmaf(sb.y, ws[4*fp+1], acc1);
                acc0 = fmaf(sa.z, ws[4*fp+2], acc0); acc1 = fmaf(sb.z, ws[4*fp+2], acc1);
                acc0 = fmaf(sa.w, ws[4*fp+3], acc0); acc1 = fmaf(sb.w, ws[4*fp+3], acc1);
            }
            g_h2[(size_t)(v0 + q2) * 64 + lane] = acc0;
            g_h2[(size_t)(v0 + q2) * 64 + 32 + lane] = acc1;
            ls += acc0 + acc1;
            lss = fmaf(acc0, acc0, lss);
            lss = fmaf(acc1, acc1, lss);
        }
        __syncwarp();
    }
    atomicAdd(&bsum[lane], ls);
    atomicAdd(&bss[lane], lss);
    __syncthreads();
    if (tid < 32) {
        atomicAdd(&g_stats[64 + tid], bsum[tid]);
        atomicAdd(&g_stats[96 + tid], bss[tid]);
    }
}

// ---------------- K7: out = relu(bn2(h2)), layout [B,V,32] ------------------
__global__ void k_output(float* __restrict__ out) {
    const int total = NV * 16;
    for (int idx = blockIdx.x * blockDim.x + threadIdx.x; idx < total;
         idx += gridDim.x * blockDim.x) {
        int v = idx >> 4;
        int j = idx & 15;
        int col = j * 4;
        int ch = col & 31;
        int b = col >> 5;
        float4 hv = *(const float4*)(g_h2 + (size_t)v * 64 + col);
        float4 r;
        r.x = fmaxf(fmaf(hv.x, g_sb[64 + ch],     g_sb[96 + ch]),     0.0f);
        r.y = fmaxf(fmaf(hv.y, g_sb[64 + ch + 1], g_sb[96 + ch + 1]), 0.0f);
        r.z = fmaxf(fmaf(hv.z, g_sb[64 + ch + 2], g_sb[96 + ch + 2]), 0.0f);
        r.w = fmaxf(fmaf(hv.w, g_sb[64 + ch + 3], g_sb[96 + ch + 3]), 0.0f);
        *(float4*)(out + (size_t)b * NV * 32 + (size_t)v * 32 + ch) = r;
    }
}

// ---------------- launch ----------------------------------------------------
extern "C" void kernel_launch(void* const* d_in, const int* in_sizes, int n_in,
                              void* d_out, int out_size) {
    const float* x    = (const float*)d_in[0];
    const int*   cols = (const int*)d_in[2];
    const float* vals = (const float*)d_in[3];
    const float* W1   = (const float*)d_in[4];
    const float* g1   = (const float*)d_in[5];
    const float* b1   = (const float*)d_in[6];
    const float* W2   = (const float*)d_in[7];
    const float* g2   = (const float*)d_in[8];
    const float* b2   = (const float*)d_in[9];
    float*       out  = (float*)d_out;

    const int GRID_G = 1184;      // gather kernels, 256 thr
    const int GRID_F = 2368;      // fused kernels, 128 thr

    k_zero_stats<<<1, 128>>>();
    k_transpose<<<2048, 256>>>(x);
    k_spmv32<<<GRID_G, 256>>>(cols, vals);
    k_fused1<<<GRID_F, 128>>>(cols, vals, W1);
    k_finalize<<<1, 32>>>(g1, b1, 0);
    k_spmv64_bn<<<GRID_G, 256>>>(cols, vals);
    k_fused2<<<GRID_F, 128>>>(cols, vals, W2);
    k_finalize<<<1, 32>>>(g2, b2, 1);
    k_output<<<2048, 256>>>(out);
}